// round 16
// baseline (speedup 1.0000x reference)
#include <cuda_runtime.h>
#include <cuda_fp16.h>
#include <math.h>
#include <stdint.h>

#define BB 4
#define TT 2048
#define CC 1024
#define HH 16
#define DH 64
#define MM (BB*TT)   // 8192

// Scratch (device globals: allocation-free per harness rules)
__device__ __half g_xh[(size_t)MM*CC];
__device__ __half g_Wh[(size_t)4*CC*CC];
__device__ __half g_Qh[(size_t)MM*CC];
__device__ __half g_Kh[(size_t)MM*CC];
__device__ __half g_Vh[(size_t)MM*CC];
__device__ __half g_Yh[(size_t)MM*CC];

// ===========================================================================
// Helpers (base sm_103 PTX only: mma.sync f16 / ldmatrix / cp.async)
// ===========================================================================
__device__ __forceinline__ uint32_t smem_u32(const void* p) {
    uint32_t a;
    asm("{ .reg .u64 t; cvta.to.shared.u64 t, %1; cvt.u32.u64 %0, t; }" : "=r"(a) : "l"(p));
    return a;
}
__device__ __forceinline__ float ex2(float x) {
    float r;
    asm("ex2.approx.f32 %0, %1;" : "=f"(r) : "f"(x));
    return r;
}
__device__ __forceinline__ uint32_t ex2h2(uint32_t x) {
    uint32_t r;
    asm("ex2.approx.f16x2 %0, %1;" : "=r"(r) : "r"(x));
    return r;
}
__device__ __forceinline__ void mma16(float* c, const uint32_t* a, uint32_t b0, uint32_t b1) {
    asm volatile(
        "mma.sync.aligned.m16n8k16.row.col.f32.f16.f16.f32 "
        "{%0,%1,%2,%3}, {%4,%5,%6,%7}, {%8,%9}, {%0,%1,%2,%3};"
        : "+f"(c[0]), "+f"(c[1]), "+f"(c[2]), "+f"(c[3])
        : "r"(a[0]), "r"(a[1]), "r"(a[2]), "r"(a[3]), "r"(b0), "r"(b1));
}
__device__ __forceinline__ void ldsm4(uint32_t* r, uint32_t addr) {
    asm volatile("ldmatrix.sync.aligned.m8n8.x4.shared.b16 {%0,%1,%2,%3}, [%4];"
                 : "=r"(r[0]), "=r"(r[1]), "=r"(r[2]), "=r"(r[3]) : "r"(addr));
}
__device__ __forceinline__ void ldsm4t(uint32_t* r, uint32_t addr) {
    asm volatile("ldmatrix.sync.aligned.m8n8.x4.trans.shared.b16 {%0,%1,%2,%3}, [%4];"
                 : "=r"(r[0]), "=r"(r[1]), "=r"(r[2]), "=r"(r[3]) : "r"(addr));
}
__device__ __forceinline__ void cp16(uint32_t dst, const void* src) {
    asm volatile("{ .reg .u64 g; cvta.to.global.u64 g, %1; "
                 "cp.async.cg.shared.global [%0], [g], 16; }"
                 :: "r"(dst), "l"(src));
}
#define CP_COMMIT() asm volatile("cp.async.commit_group;" ::: "memory")
#define CP_WAIT1()  asm volatile("cp.async.wait_group 1;" ::: "memory")

// ===========================================================================
// fp32 -> fp16 conversion pre-pass: x (8M) + 4 weight matrices (4x1M).
// 8 elems/thread.
// ===========================================================================
__global__ __launch_bounds__(256)
void cvt_kernel(const float* __restrict__ x,
                const float* __restrict__ Wq, const float* __restrict__ Wk,
                const float* __restrict__ Wv, const float* __restrict__ Wo)
{
    const size_t NX = (size_t)MM * CC;
    const size_t NW = (size_t)CC * CC;
    size_t base = ((size_t)blockIdx.x * blockDim.x + threadIdx.x) * 8;

    const float* src; __half* dst; size_t off;
    if (base < NX) { src = x; dst = g_xh; off = base; }
    else {
        size_t r = base - NX;
        int w = (int)(r / NW);
        off = r % NW;
        src = (w == 0) ? Wq : (w == 1) ? Wk : (w == 2) ? Wv : Wo;
        dst = g_Wh + (size_t)w * NW;
    }
    float4 v0 = *reinterpret_cast<const float4*>(&src[off]);
    float4 v1 = *reinterpret_cast<const float4*>(&src[off + 4]);
    __half2 h0 = __floats2half2_rn(v0.x, v0.y);
    __half2 h1 = __floats2half2_rn(v0.z, v0.w);
    __half2 h2 = __floats2half2_rn(v1.x, v1.y);
    __half2 h3 = __floats2half2_rn(v1.z, v1.w);
    *reinterpret_cast<__half2*>(&dst[off])     = h0;
    *reinterpret_cast<__half2*>(&dst[off + 2]) = h1;
    *reinterpret_cast<__half2*>(&dst[off + 4]) = h2;
    *reinterpret_cast<__half2*>(&dst[off + 6]) = h3;
}

// ===========================================================================
// fp16 GEMM: out = A*W^T + bias.  M=8192,N=1024,K=1024.
// 128x128 CTA tile, 4 warps, warp tile 64x64.
// BK=64, 3-stage cp.async, SINGLE-buffered fragments (regs ~218),
// barriers halved vs BK=32. 2 CTAs/SM (smem 110592 x2 = 221184 <= 228K).
// ===========================================================================
#define GPH 144                      // bytes per smem row (128 data + 16 pad)
#define GSTG_M (128*GPH)             // 18432 B per matrix per stage
#define GSTG_B (2*GSTG_M)            // 36864 B per stage
#define GEMM_SMEM_BYTES (3*GSTG_B)   // 110592 B

__device__ __forceinline__ void gemm_issue_h(
    const __half* __restrict__ A, const __half* __restrict__ W,
    int m0, int n0, int kb, uint32_t stg, int tid)
{
#pragma unroll
    for (int i = 0; i < 8; i++) {
        const int f   = tid + i * 128;   // 0..1023
        const int row = f >> 3;          // 0..127
        const int ch  = f & 7;           // 0..7 (16B chunks of the 128B row)
        cp16(stg + (uint32_t)(row * GPH + ch * 16),
             &A[(size_t)(m0 + row) * CC + kb * 64 + ch * 8]);
        cp16(stg + GSTG_M + (uint32_t)(row * GPH + ch * 16),
             &W[(size_t)(n0 + row) * CC + kb * 64 + ch * 8]);
    }
}

template<int OUT_MODE>
__device__ __forceinline__ void gemm_body_h(
    const __half* __restrict__ A, const __half* __restrict__ W,
    const float* __restrict__ bias, void* __restrict__ outp)
{
    extern __shared__ char smc[];
    const uint32_t sbase = smem_u32(smc);

    const int tid  = threadIdx.x;
    const int lane = tid & 31;
    const int warp = tid >> 5;          // 0..3
    const int m0 = blockIdx.y * 128;
    const int n0 = blockIdx.x * 128;
    const int wRow = (warp & 1) * 64;
    const int wCol = (warp >> 1) * 64;
    const int gq = lane >> 2;
    const int gt = lane & 3;

    float acc[4][8][4];
#pragma unroll
    for (int mf = 0; mf < 4; mf++)
#pragma unroll
        for (int nf = 0; nf < 8; nf++)
#pragma unroll
            for (int r = 0; r < 4; r++) acc[mf][nf][r] = 0.f;

    // prologue: stages for kb=0,1
    gemm_issue_h(A, W, m0, n0, 0, sbase, tid);
    CP_COMMIT();
    gemm_issue_h(A, W, m0, n0, 1, sbase + GSTG_B, tid);
    CP_COMMIT();

    const int a_row = lane & 15;
    const int a_koff = (lane >> 4) * 16;
    const int b_row = (lane >> 4) * 8 + (lane & 7);
    const int b_koff = ((lane >> 3) & 1) * 16;

    const int NKB = CC / 64;   // 16
    for (int kb = 0; kb < NKB; kb++) {
        CP_WAIT1();
        __syncthreads();

        const int s = kb % 3;
        const uint32_t Ab = sbase + s * GSTG_B;
        const uint32_t Bb = Ab + GSTG_M;

#pragma unroll
        for (int ks = 0; ks < 4; ks++) {
            const int kbyte = ks * 32;
            uint32_t af[4][4];
#pragma unroll
            for (int mf = 0; mf < 4; mf++)
                ldsm4(af[mf], Ab + (uint32_t)((wRow + mf * 16 + a_row) * GPH + a_koff + kbyte));
            uint32_t bf[8][2];
#pragma unroll
            for (int np = 0; np < 4; np++) {
                uint32_t t[4];
                ldsm4(t, Bb + (uint32_t)((wCol + np * 16 + b_row) * GPH + b_koff + kbyte));
                bf[np * 2][0] = t[0]; bf[np * 2][1] = t[1];
                bf[np * 2 + 1][0] = t[2]; bf[np * 2 + 1][1] = t[3];
            }
#pragma unroll
            for (int mf = 0; mf < 4; mf++)
#pragma unroll
                for (int nf = 0; nf < 8; nf++)
                    mma16(acc[mf][nf], af[mf], bf[nf][0], bf[nf][1]);
        }

        if (kb + 2 < NKB) {
            gemm_issue_h(A, W, m0, n0, kb + 2, sbase + ((kb + 2) % 3) * GSTG_B, tid);
        }
        CP_COMMIT();
    }

#pragma unroll
    for (int nf = 0; nf < 8; nf++) {
        const int col = n0 + wCol + nf * 8 + gt * 2;
        const float b0 = bias[col], b1 = bias[col + 1];
#pragma unroll
        for (int mf = 0; mf < 4; mf++) {
            const int row = m0 + wRow + mf * 16 + gq;
#pragma unroll
            for (int half = 0; half < 2; half++) {
                const int r = row + half * 8;
                const float v0 = acc[mf][nf][half * 2 + 0] + b0;
                const float v1 = acc[mf][nf][half * 2 + 1] + b1;
                if (OUT_MODE == 1) {
                    const int b = r / TT, t = r % TT;
                    const int h = col >> 6, d = col & 63;
                    __half* out = (__half*)outp;
                    *reinterpret_cast<__half2*>(
                        &out[(((size_t)(b * HH + h) * TT + t) * DH) + d]) =
                        __floats2half2_rn(v0, v1);
                } else {
                    float* out = (float*)outp;
                    *reinterpret_cast<float2*>(&out[(size_t)r * CC + col]) =
                        make_float2(v0, v1);
                }
            }
        }
    }
}

__global__ __launch_bounds__(128, 2)
void gemm_qkv(const float* __restrict__ bq, const float* __restrict__ bk,
              const float* __restrict__ bv)
{
    const float* bias; __half* out; const __half* W;
    if (blockIdx.z == 0)      { W = g_Wh;              bias = bq; out = g_Qh; }
    else if (blockIdx.z == 1) { W = g_Wh + (size_t)CC*CC;   bias = bk; out = g_Kh; }
    else                      { W = g_Wh + (size_t)2*CC*CC; bias = bv; out = g_Vh; }
    gemm_body_h<1>(g_xh, W, bias, out);
}

__global__ __launch_bounds__(128, 2)
void gemm_out(const float* __restrict__ bo, float* __restrict__ out)
{
    gemm_body_h<0>(g_Yh, g_Wh + (size_t)3*CC*CC, bo, out);
}

// ===========================================================================
// Flash attention (round-14/15 config, EXACT): causal, fp16 mma m16n8k16,
// 4 warps x M=32, LPT order, 128-key K/V buffers as two 64-key sub-tiles.
// ===========================================================================
#define FPH 72                        // halfs per smem row (144 B)
#define KRH(b) ((b)*128*FPH)
#define VRH(b) (2*128*FPH + (b)*128*FPH)
#define PHH    (4*128*FPH)
#define FL_BYTES ((PHH + 128*FPH)*2)  // 92160 B

__device__ __forceinline__ void flash_issue_h(
    const __half* __restrict__ Kb, const __half* __restrict__ Vb,
    int k0, int buf, uint32_t sbase, int tid)
{
#pragma unroll
    for (int i = 0; i < 8; i++) {
        const int f   = tid + i * 128;   // 0..1023
        const int row = f >> 3;          // 0..127 (key)
        const int ch  = f & 7;
        cp16(sbase + (uint32_t)(KRH(buf) * 2 + row * FPH * 2 + ch * 16),
             &Kb[(size_t)(k0 + row) * DH + ch * 8]);
        cp16(sbase + (uint32_t)(VRH(buf) * 2 + row * FPH * 2 + ch * 16),
             &Vb[(size_t)(k0 + row) * DH + ch * 8]);
    }
}

__global__ __launch_bounds__(128, 2)
void flash_mma(float* __restrict__ dummy)
{
    extern __shared__ char smc[];
    __half* smh = reinterpret_cast<__half*>(smc);
    const uint32_t sbase = smem_u32(smc);

    const int tid  = threadIdx.x;
    const int lane = tid & 31;
    const int w    = tid >> 5;      // warp 0..3, rows w*32..w*32+31
    const int gq   = lane >> 2;
    const int gt   = lane & 3;

    const int bh = blockIdx.y;
    const int qi = (int)(gridDim.x - 1 - blockIdx.x);   // LPT: longest first
    const int q0 = qi << 7;

    const __half* Qb = g_Qh + (size_t)bh * TT * DH;
    const __half* Kb = g_Kh + (size_t)bh * TT * DH;
    const __half* Vb = g_Vh + (size_t)bh * TT * DH;

    const float NEG = -1e30f;
    const float SC = 0.18033688011112042f;   // 0.125 * log2(e)
    const int npt = qi + 1;                  // 128-key tiles needed

    flash_issue_h(Kb, Vb, 0, 0, sbase, tid);
    CP_COMMIT();
    flash_issue_h(Kb, Vb, 128, 1, sbase, tid);   // safe: q0+128 <= TT
    CP_COMMIT();

    // ---- stage Q tile (fp16) into P region: 128 rows x 64 halfs ----
#pragma unroll
    for (int i = 0; i < 8; i++) {
        const int f   = tid + i * 128;
        const int row = f >> 3;
        const int ch  = f & 7;
        *reinterpret_cast<uint4*>(&smh[PHH + row * FPH + ch * 8]) =
            *reinterpret_cast<const uint4*>(&Qb[(size_t)(q0 + row) * DH + ch * 8]);
    }
    __syncthreads();

    const int a_row  = lane & 15;
    const int a_koff = (lane >> 4) * 16;
    const int b_row  = (lane >> 4) * 8 + (lane & 7);
    const int b_koff = ((lane >> 3) & 1) * 16;
    const int t_key  = ((lane >> 3) & 1) * 8 + (lane & 7);
    const int t_dh   = (lane >> 4);

    uint32_t qf[2][4][4];
#pragma unroll
    for (int mf = 0; mf < 2; mf++)
#pragma unroll
        for (int kd = 0; kd < 4; kd++)
            ldsm4(qf[mf][kd], sbase + (uint32_t)((PHH + (w * 32 + mf * 16 + a_row) * FPH) * 2
                                                 + a_koff + kd * 32));
    __syncthreads();   // all warps done reading Q before P overwrites

    float acc[2][8][4];
#pragma unroll
    for (int mf = 0; mf < 2; mf++)
#pragma unroll
        for (int nf = 0; nf < 8; nf++)
#pragma unroll
            for (int r = 0; r < 4; r++) acc[mf][nf][r] = 0.f;
    float mrun[2][2] = {{NEG, NEG}, {NEG, NEG}};
    float lrun[2][2] = {{0.f, 0.f}, {0.f, 0.f}};

    for (int pt = 0; pt < npt; pt++) {
        const int cb = pt & 1;

        CP_WAIT1();
        __syncthreads();

#pragma unroll
        for (int hh = 0; hh < 2; hh++) {
            const int k0 = pt * 128 + hh * 64;
            const int krow0 = hh * 64;   // row offset within the 128-key buffer
            const bool active = (k0 <= q0 + w * 32 + 31);
            if (active) {
                // ---- S = Q K^T ----
                float sc[2][8][4];
#pragma unroll
                for (int mf = 0; mf < 2; mf++)
#pragma unroll
                    for (int nf = 0; nf < 8; nf++)
#pragma unroll
                        for (int r = 0; r < 4; r++) sc[mf][nf][r] = 0.f;

#pragma unroll
                for (int kd = 0; kd < 4; kd++) {
#pragma unroll
                    for (int np = 0; np < 4; np++) {
                        uint32_t t[4];
                        ldsm4(t, sbase + (uint32_t)((KRH(cb) + (krow0 + np * 16 + b_row) * FPH) * 2
                                                    + b_koff + kd * 32));
#pragma unroll
                        for (int mf = 0; mf < 2; mf++) {
                            mma16(sc[mf][np * 2],     qf[mf][kd], t[0], t[1]);
                            mma16(sc[mf][np * 2 + 1], qf[mf][kd], t[2], t[3]);
                        }
                    }
                }

                // ---- per-m-frag softmax update ----
#pragma unroll
                for (int mf = 0; mf < 2; mf++) {
                    const int r0g = q0 + w * 32 + mf * 16 + gq;
                    const int r1g = r0g + 8;
                    float mx0 = NEG, mx1 = NEG;
#pragma unroll
                    for (int nf = 0; nf < 8; nf++) {
                        const int c0 = k0 + nf * 8 + 2 * gt;
                        sc[mf][nf][0] = (c0     <= r0g) ? sc[mf][nf][0] * SC : NEG;
                        sc[mf][nf][1] = (c0 + 1 <= r0g) ? sc[mf][nf][1] * SC : NEG;
                        sc[mf][nf][2] = (c0     <= r1g) ? sc[mf][nf][2] * SC : NEG;
                        sc[mf][nf][3] = (c0 + 1 <= r1g) ? sc[mf][nf][3] * SC : NEG;
                        mx0 = fmaxf(mx0, fmaxf(sc[mf][nf][0], sc[mf][nf][1]));
                        mx1 = fmaxf(mx1, fmaxf(sc[mf][nf][2], sc[mf][nf][3]));
                    }
                    mx0 = fmaxf(mx0, __shfl_xor_sync(0xffffffffu, mx0, 1));
                    mx0 = fmaxf(mx0, __shfl_xor_sync(0xffffffffu, mx0, 2));
                    mx1 = fmaxf(mx1, __shfl_xor_sync(0xffffffffu, mx1, 1));
                    mx1 = fmaxf(mx1, __shfl_xor_sync(0xffffffffu, mx1, 2));

                    const float mn0 = fmaxf(mrun[mf][0], mx0);
                    const float mn1 = fmaxf(mrun[mf][1], mx1);
                    const float a0 = ex2(mrun[mf][0] - mn0);
                    const float a1 = ex2(mrun[mf][1] - mn1);
                    float ls0 = 0.f, ls1 = 0.f;

#pragma unroll
                    for (int nf = 0; nf < 8; nf++) {
                        __half2 ha = __floats2half2_rn(sc[mf][nf][0] - mn0, sc[mf][nf][1] - mn0);
                        __half2 hb = __floats2half2_rn(sc[mf][nf][2] - mn1, sc[mf][nf][3] - mn1);
                        uint32_t ea = ex2h2(*reinterpret_cast<uint32_t*>(&ha));
                        uint32_t eb = ex2h2(*reinterpret_cast<uint32_t*>(&hb));
                        float2 fa = __half22float2(*reinterpret_cast<__half2*>(&ea));
                        float2 fb = __half22float2(*reinterpret_cast<__half2*>(&eb));
                        ls0 += fa.x + fa.y;
                        ls1 += fb.x + fb.y;
                        const int col = nf * 8 + 2 * gt;
                        *reinterpret_cast<uint32_t*>(
                            &smh[PHH + (w * 32 + mf * 16 + gq) * FPH + col]) = ea;
                        *reinterpret_cast<uint32_t*>(
                            &smh[PHH + (w * 32 + mf * 16 + gq + 8) * FPH + col]) = eb;
                    }
                    ls0 += __shfl_xor_sync(0xffffffffu, ls0, 1);
                    ls0 += __shfl_xor_sync(0xffffffffu, ls0, 2);
                    ls1 += __shfl_xor_sync(0xffffffffu, ls1, 1);
                    ls1 += __shfl_xor_sync(0xffffffffu, ls1, 2);
                    mrun[mf][0] = mn0; mrun[mf][1] = mn1;
                    lrun[mf][0] = lrun[mf][0] * a0 + ls0;
                    lrun[mf][1] = lrun[mf][1] * a1 + ls1;
#pragma unroll
                    for (int nf = 0; nf < 8; nf++) {
                        acc[mf][nf][0] *= a0; acc[mf][nf][1] *= a0;
                        acc[mf][nf][2] *= a1; acc[mf][nf][3] *= a1;
                    }
                }

                __syncwarp();   // P rows are warp-private

                // ---- acc += P * V ----
#pragma unroll
                for (int kk = 0; kk < 4; kk++) {
                    uint32_t ap[2][4];
#pragma unroll
                    for (int mf = 0; mf < 2; mf++)
                        ldsm4(ap[mf], sbase + (uint32_t)((PHH + (w * 32 + mf * 16 + a_row) * FPH) * 2
                                                         + a_koff + kk * 32));
#pragma unroll
                    for (int np = 0; np < 4; np++) {
                        uint32_t t[4];
                        const int key = krow0 + kk * 16 + t_key;
                        const int dhb = (np * 2 + t_dh) * 16;
                        ldsm4t(t, sbase + (uint32_t)((VRH(cb) + key * FPH) * 2 + dhb));
#pragma unroll
                        for (int mf = 0; mf < 2; mf++) {
                            mma16(acc[mf][np * 2],     ap[mf], t[0], t[1]);
                            mma16(acc[mf][np * 2 + 1], ap[mf], t[2], t[3]);
                        }
                    }
                }
                __syncwarp();   // P reads done before next sub-tile overwrites
            }
        }
        __syncthreads();   // all warps done with buffer cb

        if (pt + 2 < npt)
            flash_issue_h(Kb, Vb, (pt + 2) * 128, cb, sbase, tid);
        CP_COMMIT();
    }

    // ---- epilogue: normalize, write Yh fp16 [B,T,C] ----
    const int b = bh >> 4, h = bh & 15;
#pragma unroll
    for (int mf = 0; mf < 2; mf++) {
        const float i0 = 1.f / lrun[mf][0];
        const float i1 = 1.f / lrun[mf][1];
        const int r0 = q0 + w * 32 + mf * 16 + gq;
        const int r1 = r0 + 8;
        const size_t base0 = ((size_t)b * TT + r0) * CC + h * DH;
        const size_t base1 = ((size_t)b * TT + r1) * CC + h * DH;
#pragma unroll
        for (int nf = 0; nf < 8; nf++) {
            const int col = nf * 8 + 2 * gt;
            *reinterpret_cast<__half2*>(&g_Yh[base0 + col]) =
                __floats2half2_rn(acc[mf][nf][0] * i0, acc[mf][nf][1] * i0);
            *reinterpret_cast<__half2*>(&g_Yh[base1 + col]) =
                __floats2half2_rn(acc[mf][nf][2] * i1, acc[mf][nf][3] * i1);
        }
    }
}

// ---------------------------------------------------------------------------
extern "C" void kernel_launch(void* const* d_in, const int* in_sizes, int n_in,
                              void* d_out, int out_size)
{
    const float* x  = (const float*)d_in[0];
    const float* Wq = (const float*)d_in[1];
    const float* bq = (const float*)d_in[2];
    const float* Wk = (const float*)d_in[3];
    const float* bk = (const float*)d_in[4];
    const float* Wv = (const float*)d_in[5];
    const float* bv = (const float*)d_in[6];
    const float* Wo = (const float*)d_in[7];
    const float* bo = (const float*)d_in[8];
    float* out = (float*)d_out;

    cudaFuncSetAttribute(gemm_qkv,
                         cudaFuncAttributeMaxDynamicSharedMemorySize, GEMM_SMEM_BYTES);
    cudaFuncSetAttribute(gemm_out,
                         cudaFuncAttributeMaxDynamicSharedMemorySize, GEMM_SMEM_BYTES);
    cudaFuncSetAttribute(flash_mma,
                         cudaFuncAttributeMaxDynamicSharedMemorySize, FL_BYTES);

    const size_t NCV = ((size_t)MM * CC + (size_t)4 * CC * CC) / 8;
    cvt_kernel<<<(unsigned)(NCV / 256), 256>>>(x, Wq, Wk, Wv, Wo);

    gemm_qkv<<<dim3(CC / 128, MM / 128, 3), 128, GEMM_SMEM_BYTES>>>(bq, bk, bv);

    flash_mma<<<dim3(TT / 128, BB * HH), 128, FL_BYTES>>>(out);

    gemm_out<<<dim3(CC / 128, MM / 128), 128, GEMM_SMEM_BYTES>>>(bo, out);
}

// round 17
// speedup vs baseline: 1.0347x; 1.0347x over previous
#include <cuda_runtime.h>
#include <cuda_fp16.h>
#include <math.h>
#include <stdint.h>

#define BB 4
#define TT 2048
#define CC 1024
#define HH 16
#define DH 64
#define MM (BB*TT)   // 8192

// Scratch (device globals: allocation-free per harness rules)
__device__ __half g_xh[(size_t)MM*CC];
__device__ __half g_Wh[(size_t)4*CC*CC];
__device__ __half g_Qh[(size_t)MM*CC];
__device__ __half g_Kh[(size_t)MM*CC];
__device__ __half g_Vh[(size_t)MM*CC];
__device__ __half g_Yh[(size_t)MM*CC];

// ===========================================================================
// Helpers (base sm_103 PTX only: mma.sync f16 / ldmatrix / cp.async)
// ===========================================================================
__device__ __forceinline__ uint32_t smem_u32(const void* p) {
    uint32_t a;
    asm("{ .reg .u64 t; cvta.to.shared.u64 t, %1; cvt.u32.u64 %0, t; }" : "=r"(a) : "l"(p));
    return a;
}
__device__ __forceinline__ float ex2(float x) {
    float r;
    asm("ex2.approx.f32 %0, %1;" : "=f"(r) : "f"(x));
    return r;
}
__device__ __forceinline__ uint32_t ex2h2(uint32_t x) {
    uint32_t r;
    asm("ex2.approx.f16x2 %0, %1;" : "=r"(r) : "r"(x));
    return r;
}
__device__ __forceinline__ void mma16(float* c, const uint32_t* a, uint32_t b0, uint32_t b1) {
    asm volatile(
        "mma.sync.aligned.m16n8k16.row.col.f32.f16.f16.f32 "
        "{%0,%1,%2,%3}, {%4,%5,%6,%7}, {%8,%9}, {%0,%1,%2,%3};"
        : "+f"(c[0]), "+f"(c[1]), "+f"(c[2]), "+f"(c[3])
        : "r"(a[0]), "r"(a[1]), "r"(a[2]), "r"(a[3]), "r"(b0), "r"(b1));
}
__device__ __forceinline__ void ldsm4(uint32_t* r, uint32_t addr) {
    asm volatile("ldmatrix.sync.aligned.m8n8.x4.shared.b16 {%0,%1,%2,%3}, [%4];"
                 : "=r"(r[0]), "=r"(r[1]), "=r"(r[2]), "=r"(r[3]) : "r"(addr));
}
__device__ __forceinline__ void ldsm4t(uint32_t* r, uint32_t addr) {
    asm volatile("ldmatrix.sync.aligned.m8n8.x4.trans.shared.b16 {%0,%1,%2,%3}, [%4];"
                 : "=r"(r[0]), "=r"(r[1]), "=r"(r[2]), "=r"(r[3]) : "r"(addr));
}
__device__ __forceinline__ void cp16(uint32_t dst, const void* src) {
    asm volatile("{ .reg .u64 g; cvta.to.global.u64 g, %1; "
                 "cp.async.cg.shared.global [%0], [g], 16; }"
                 :: "r"(dst), "l"(src));
}
// L1-allocating variant: flash K/V streams are shared between the 2
// co-resident CTAs (same bh) -> second CTA hits L1 instead of L2.
__device__ __forceinline__ void cp16ca(uint32_t dst, const void* src) {
    asm volatile("{ .reg .u64 g; cvta.to.global.u64 g, %1; "
                 "cp.async.ca.shared.global [%0], [g], 16; }"
                 :: "r"(dst), "l"(src));
}
#define CP_COMMIT() asm volatile("cp.async.commit_group;" ::: "memory")
#define CP_WAIT2()  asm volatile("cp.async.wait_group 2;" ::: "memory")
#define CP_WAIT1()  asm volatile("cp.async.wait_group 1;" ::: "memory")

// ===========================================================================
// fp32 -> fp16 conversion pre-pass: x (8M) + 4 weight matrices (4x1M).
// 8 elems/thread.
// ===========================================================================
__global__ __launch_bounds__(256)
void cvt_kernel(const float* __restrict__ x,
                const float* __restrict__ Wq, const float* __restrict__ Wk,
                const float* __restrict__ Wv, const float* __restrict__ Wo)
{
    const size_t NX = (size_t)MM * CC;
    const size_t NW = (size_t)CC * CC;
    size_t base = ((size_t)blockIdx.x * blockDim.x + threadIdx.x) * 8;

    const float* src; __half* dst; size_t off;
    if (base < NX) { src = x; dst = g_xh; off = base; }
    else {
        size_t r = base - NX;
        int w = (int)(r / NW);
        off = r % NW;
        src = (w == 0) ? Wq : (w == 1) ? Wk : (w == 2) ? Wv : Wo;
        dst = g_Wh + (size_t)w * NW;
    }
    float4 v0 = *reinterpret_cast<const float4*>(&src[off]);
    float4 v1 = *reinterpret_cast<const float4*>(&src[off + 4]);
    __half2 h0 = __floats2half2_rn(v0.x, v0.y);
    __half2 h1 = __floats2half2_rn(v0.z, v0.w);
    __half2 h2 = __floats2half2_rn(v1.x, v1.y);
    __half2 h3 = __floats2half2_rn(v1.z, v1.w);
    *reinterpret_cast<__half2*>(&dst[off])     = h0;
    *reinterpret_cast<__half2*>(&dst[off + 2]) = h1;
    *reinterpret_cast<__half2*>(&dst[off + 4]) = h2;
    *reinterpret_cast<__half2*>(&dst[off + 6]) = h3;
}

// ===========================================================================
// fp16 GEMM (round-12 converged config, FROZEN): out = A*W^T + bias.
// 128x128 CTA tile, 4 warps, warp tile 64x64, BK=32, 4-stage cp.async,
// single-buffered fragments, issue AFTER the MMA block, 2 CTAs/SM.
// ===========================================================================
#define GPH 80
#define GSTG_B (128*GPH)
#define GEMM_SMEM_BYTES (8*GSTG_B)   // 81920 B

__device__ __forceinline__ void gemm_issue_h(
    const __half* __restrict__ A, const __half* __restrict__ W,
    int m0, int n0, int kb, uint32_t abase, uint32_t bbase, int tid)
{
#pragma unroll
    for (int i = 0; i < 4; i++) {
        const int f   = tid + i * 128;
        const int row = f >> 2;
        const int ch  = f & 3;
        cp16(abase + (uint32_t)(row * GPH + ch * 16),
             &A[(size_t)(m0 + row) * CC + kb * 32 + ch * 8]);
        cp16(bbase + (uint32_t)(row * GPH + ch * 16),
             &W[(size_t)(n0 + row) * CC + kb * 32 + ch * 8]);
    }
}

template<int OUT_MODE>
__device__ __forceinline__ void gemm_body_h(
    const __half* __restrict__ A, const __half* __restrict__ W,
    const float* __restrict__ bias, void* __restrict__ outp)
{
    extern __shared__ char smc[];
    const uint32_t sbase = smem_u32(smc);

    const int tid  = threadIdx.x;
    const int lane = tid & 31;
    const int warp = tid >> 5;
    const int m0 = blockIdx.y * 128;
    const int n0 = blockIdx.x * 128;
    const int wRow = (warp & 1) * 64;
    const int wCol = (warp >> 1) * 64;
    const int gq = lane >> 2;
    const int gt = lane & 3;

    float acc[4][8][4];
#pragma unroll
    for (int mf = 0; mf < 4; mf++)
#pragma unroll
        for (int nf = 0; nf < 8; nf++)
#pragma unroll
            for (int r = 0; r < 4; r++) acc[mf][nf][r] = 0.f;

#pragma unroll
    for (int s = 0; s < 3; s++) {
        gemm_issue_h(A, W, m0, n0, s,
                     sbase + s * GSTG_B, sbase + (4 + s) * GSTG_B, tid);
        CP_COMMIT();
    }

    const int a_row = lane & 15;
    const int a_koff = (lane >> 4) * 16;
    const int b_row = (lane >> 4) * 8 + (lane & 7);
    const int b_koff = ((lane >> 3) & 1) * 16;

    const int NKB = CC / 32;
    for (int kb = 0; kb < NKB; kb++) {
        CP_WAIT2();
        __syncthreads();

        const int s = kb & 3;
        const uint32_t Ab = sbase + s * GSTG_B;
        const uint32_t Bb = sbase + (4 + s) * GSTG_B;

#pragma unroll
        for (int ks = 0; ks < 2; ks++) {
            const int kbyte = ks * 32;
            uint32_t af[4][4];
#pragma unroll
            for (int mf = 0; mf < 4; mf++)
                ldsm4(af[mf], Ab + (uint32_t)((wRow + mf * 16 + a_row) * GPH + a_koff + kbyte));
            uint32_t bf[8][2];
#pragma unroll
            for (int np = 0; np < 4; np++) {
                uint32_t t[4];
                ldsm4(t, Bb + (uint32_t)((wCol + np * 16 + b_row) * GPH + b_koff + kbyte));
                bf[np * 2][0] = t[0]; bf[np * 2][1] = t[1];
                bf[np * 2 + 1][0] = t[2]; bf[np * 2 + 1][1] = t[3];
            }
#pragma unroll
            for (int mf = 0; mf < 4; mf++)
#pragma unroll
                for (int nf = 0; nf < 8; nf++)
                    mma16(acc[mf][nf], af[mf], bf[nf][0], bf[nf][1]);
        }

        if (kb + 3 < NKB) {
            const int sn = (kb + 3) & 3;
            gemm_issue_h(A, W, m0, n0, kb + 3,
                         sbase + sn * GSTG_B, sbase + (4 + sn) * GSTG_B, tid);
        }
        CP_COMMIT();
    }

#pragma unroll
    for (int nf = 0; nf < 8; nf++) {
        const int col = n0 + wCol + nf * 8 + gt * 2;
        const float b0 = bias[col], b1 = bias[col + 1];
#pragma unroll
        for (int mf = 0; mf < 4; mf++) {
            const int row = m0 + wRow + mf * 16 + gq;
#pragma unroll
            for (int half = 0; half < 2; half++) {
                const int r = row + half * 8;
                const float v0 = acc[mf][nf][half * 2 + 0] + b0;
                const float v1 = acc[mf][nf][half * 2 + 1] + b1;
                if (OUT_MODE == 1) {
                    const int b = r / TT, t = r % TT;
                    const int h = col >> 6, d = col & 63;
                    __half* out = (__half*)outp;
                    *reinterpret_cast<__half2*>(
                        &out[(((size_t)(b * HH + h) * TT + t) * DH) + d]) =
                        __floats2half2_rn(v0, v1);
                } else {
                    float* out = (float*)outp;
                    *reinterpret_cast<float2*>(&out[(size_t)r * CC + col]) =
                        make_float2(v0, v1);
                }
            }
        }
    }
}

__global__ __launch_bounds__(128, 2)
void gemm_qkv(const float* __restrict__ bq, const float* __restrict__ bk,
              const float* __restrict__ bv)
{
    const float* bias; __half* out; const __half* W;
    if (blockIdx.z == 0)      { W = g_Wh;              bias = bq; out = g_Qh; }
    else if (blockIdx.z == 1) { W = g_Wh + (size_t)CC*CC;   bias = bk; out = g_Kh; }
    else                      { W = g_Wh + (size_t)2*CC*CC; bias = bv; out = g_Vh; }
    gemm_body_h<1>(g_xh, W, bias, out);
}

__global__ __launch_bounds__(128, 2)
void gemm_out(const float* __restrict__ bo, float* __restrict__ out)
{
    gemm_body_h<0>(g_Yh, g_Wh + (size_t)3*CC*CC, bo, out);
}

// ===========================================================================
// Flash attention (round-15 config): causal, fp16 mma m16n8k16,
// 4 warps x M=32, LPT order, 128-key K/V buffers as two 64-key sub-tiles.
// NEW: K/V staged with cp.async.ca (L1-allocating; co-resident CTA shares bh).
// ===========================================================================
#define FPH 72                        // halfs per smem row (144 B)
#define KRH(b) ((b)*128*FPH)
#define VRH(b) (2*128*FPH + (b)*128*FPH)
#define PHH    (4*128*FPH)
#define FL_BYTES ((PHH + 128*FPH)*2)  // 92160 B

__device__ __forceinline__ void flash_issue_h(
    const __half* __restrict__ Kb, const __half* __restrict__ Vb,
    int k0, int buf, uint32_t sbase, int tid)
{
#pragma unroll
    for (int i = 0; i < 8; i++) {
        const int f   = tid + i * 128;   // 0..1023
        const int row = f >> 3;          // 0..127 (key)
        const int ch  = f & 7;
        cp16ca(sbase + (uint32_t)(KRH(buf) * 2 + row * FPH * 2 + ch * 16),
               &Kb[(size_t)(k0 + row) * DH + ch * 8]);
        cp16ca(sbase + (uint32_t)(VRH(buf) * 2 + row * FPH * 2 + ch * 16),
               &Vb[(size_t)(k0 + row) * DH + ch * 8]);
    }
}

__global__ __launch_bounds__(128, 2)
void flash_mma(float* __restrict__ dummy)
{
    extern __shared__ char smc[];
    __half* smh = reinterpret_cast<__half*>(smc);
    const uint32_t sbase = smem_u32(smc);

    const int tid  = threadIdx.x;
    const int lane = tid & 31;
    const int w    = tid >> 5;      // warp 0..3, rows w*32..w*32+31
    const int gq   = lane >> 2;
    const int gt   = lane & 3;

    const int bh = blockIdx.y;
    const int qi = (int)(gridDim.x - 1 - blockIdx.x);   // LPT: longest first
    const int q0 = qi << 7;

    const __half* Qb = g_Qh + (size_t)bh * TT * DH;
    const __half* Kb = g_Kh + (size_t)bh * TT * DH;
    const __half* Vb = g_Vh + (size_t)bh * TT * DH;

    const float NEG = -1e30f;
    const float SC = 0.18033688011112042f;   // 0.125 * log2(e)
    const int npt = qi + 1;                  // 128-key tiles needed

    flash_issue_h(Kb, Vb, 0, 0, sbase, tid);
    CP_COMMIT();
    flash_issue_h(Kb, Vb, 128, 1, sbase, tid);   // safe: q0+128 <= TT
    CP_COMMIT();

    // ---- stage Q tile (fp16) into P region: 128 rows x 64 halfs ----
#pragma unroll
    for (int i = 0; i < 8; i++) {
        const int f   = tid + i * 128;
        const int row = f >> 3;
        const int ch  = f & 7;
        *reinterpret_cast<uint4*>(&smh[PHH + row * FPH + ch * 8]) =
            *reinterpret_cast<const uint4*>(&Qb[(size_t)(q0 + row) * DH + ch * 8]);
    }
    __syncthreads();

    const int a_row  = lane & 15;
    const int a_koff = (lane >> 4) * 16;
    const int b_row  = (lane >> 4) * 8 + (lane & 7);
    const int b_koff = ((lane >> 3) & 1) * 16;
    const int t_key  = ((lane >> 3) & 1) * 8 + (lane & 7);
    const int t_dh   = (lane >> 4);

    uint32_t qf[2][4][4];
#pragma unroll
    for (int mf = 0; mf < 2; mf++)
#pragma unroll
        for (int kd = 0; kd < 4; kd++)
            ldsm4(qf[mf][kd], sbase + (uint32_t)((PHH + (w * 32 + mf * 16 + a_row) * FPH) * 2
                                                 + a_koff + kd * 32));
    __syncthreads();   // all warps done reading Q before P overwrites

    float acc[2][8][4];
#pragma unroll
    for (int mf = 0; mf < 2; mf++)
#pragma unroll
        for (int nf = 0; nf < 8; nf++)
#pragma unroll
            for (int r = 0; r < 4; r++) acc[mf][nf][r] = 0.f;
    float mrun[2][2] = {{NEG, NEG}, {NEG, NEG}};
    float lrun[2][2] = {{0.f, 0.f}, {0.f, 0.f}};

    for (int pt = 0; pt < npt; pt++) {
        const int cb = pt & 1;

        CP_WAIT1();
        __syncthreads();

#pragma unroll
        for (int hh = 0; hh < 2; hh++) {
            const int k0 = pt * 128 + hh * 64;
            const int krow0 = hh * 64;   // row offset within the 128-key buffer
            const bool active = (k0 <= q0 + w * 32 + 31);
            if (active) {
                // ---- S = Q K^T ----
                float sc[2][8][4];
#pragma unroll
                for (int mf = 0; mf < 2; mf++)
#pragma unroll
                    for (int nf = 0; nf < 8; nf++)
#pragma unroll
                        for (int r = 0; r < 4; r++) sc[mf][nf][r] = 0.f;

#pragma unroll
                for (int kd = 0; kd < 4; kd++) {
#pragma unroll
                    for (int np = 0; np < 4; np++) {
                        uint32_t t[4];
                        ldsm4(t, sbase + (uint32_t)((KRH(cb) + (krow0 + np * 16 + b_row) * FPH) * 2
                                                    + b_koff + kd * 32));
#pragma unroll
                        for (int mf = 0; mf < 2; mf++) {
                            mma16(sc[mf][np * 2],     qf[mf][kd], t[0], t[1]);
                            mma16(sc[mf][np * 2 + 1], qf[mf][kd], t[2], t[3]);
                        }
                    }
                }

                // ---- per-m-frag softmax update ----
#pragma unroll
                for (int mf = 0; mf < 2; mf++) {
                    const int r0g = q0 + w * 32 + mf * 16 + gq;
                    const int r1g = r0g + 8;
                    float mx0 = NEG, mx1 = NEG;
#pragma unroll
                    for (int nf = 0; nf < 8; nf++) {
                        const int c0 = k0 + nf * 8 + 2 * gt;
                        sc[mf][nf][0] = (c0     <= r0g) ? sc[mf][nf][0] * SC : NEG;
                        sc[mf][nf][1] = (c0 + 1 <= r0g) ? sc[mf][nf][1] * SC : NEG;
                        sc[mf][nf][2] = (c0     <= r1g) ? sc[mf][nf][2] * SC : NEG;
                        sc[mf][nf][3] = (c0 + 1 <= r1g) ? sc[mf][nf][3] * SC : NEG;
                        mx0 = fmaxf(mx0, fmaxf(sc[mf][nf][0], sc[mf][nf][1]));
                        mx1 = fmaxf(mx1, fmaxf(sc[mf][nf][2], sc[mf][nf][3]));
                    }
                    mx0 = fmaxf(mx0, __shfl_xor_sync(0xffffffffu, mx0, 1));
                    mx0 = fmaxf(mx0, __shfl_xor_sync(0xffffffffu, mx0, 2));
                    mx1 = fmaxf(mx1, __shfl_xor_sync(0xffffffffu, mx1, 1));
                    mx1 = fmaxf(mx1, __shfl_xor_sync(0xffffffffu, mx1, 2));

                    const float mn0 = fmaxf(mrun[mf][0], mx0);
                    const float mn1 = fmaxf(mrun[mf][1], mx1);
                    const float a0 = ex2(mrun[mf][0] - mn0);
                    const float a1 = ex2(mrun[mf][1] - mn1);
                    float ls0 = 0.f, ls1 = 0.f;

#pragma unroll
                    for (int nf = 0; nf < 8; nf++) {
                        __half2 ha = __floats2half2_rn(sc[mf][nf][0] - mn0, sc[mf][nf][1] - mn0);
                        __half2 hb = __floats2half2_rn(sc[mf][nf][2] - mn1, sc[mf][nf][3] - mn1);
                        uint32_t ea = ex2h2(*reinterpret_cast<uint32_t*>(&ha));
                        uint32_t eb = ex2h2(*reinterpret_cast<uint32_t*>(&hb));
                        float2 fa = __half22float2(*reinterpret_cast<__half2*>(&ea));
                        float2 fb = __half22float2(*reinterpret_cast<__half2*>(&eb));
                        ls0 += fa.x + fa.y;
                        ls1 += fb.x + fb.y;
                        const int col = nf * 8 + 2 * gt;
                        *reinterpret_cast<uint32_t*>(
                            &smh[PHH + (w * 32 + mf * 16 + gq) * FPH + col]) = ea;
                        *reinterpret_cast<uint32_t*>(
                            &smh[PHH + (w * 32 + mf * 16 + gq + 8) * FPH + col]) = eb;
                    }
                    ls0 += __shfl_xor_sync(0xffffffffu, ls0, 1);
                    ls0 += __shfl_xor_sync(0xffffffffu, ls0, 2);
                    ls1 += __shfl_xor_sync(0xffffffffu, ls1, 1);
                    ls1 += __shfl_xor_sync(0xffffffffu, ls1, 2);
                    mrun[mf][0] = mn0; mrun[mf][1] = mn1;
                    lrun[mf][0] = lrun[mf][0] * a0 + ls0;
                    lrun[mf][1] = lrun[mf][1] * a1 + ls1;
#pragma unroll
                    for (int nf = 0; nf < 8; nf++) {
                        acc[mf][nf][0] *= a0; acc[mf][nf][1] *= a0;
                        acc[mf][nf][2] *= a1; acc[mf][nf][3] *= a1;
                    }
                }

                __syncwarp();   // P rows are warp-private

                // ---- acc += P * V ----
#pragma unroll
                for (int kk = 0; kk < 4; kk++) {
                    uint32_t ap[2][4];
#pragma unroll
                    for (int mf = 0; mf < 2; mf++)
                        ldsm4(ap[mf], sbase + (uint32_t)((PHH + (w * 32 + mf * 16 + a_row) * FPH) * 2
                                                         + a_koff + kk * 32));
#pragma unroll
                    for (int np = 0; np < 4; np++) {
                        uint32_t t[4];
                        const int key = krow0 + kk * 16 + t_key;
                        const int dhb = (np * 2 + t_dh) * 16;
                        ldsm4t(t, sbase + (uint32_t)((VRH(cb) + key * FPH) * 2 + dhb));
#pragma unroll
                        for (int mf = 0; mf < 2; mf++) {
                            mma16(acc[mf][np * 2],     ap[mf], t[0], t[1]);
                            mma16(acc[mf][np * 2 + 1], ap[mf], t[2], t[3]);
                        }
                    }
                }
                __syncwarp();   // P reads done before next sub-tile overwrites
            }
        }
        __syncthreads();   // all warps done with buffer cb

        if (pt + 2 < npt)
            flash_issue_h(Kb, Vb, (pt + 2) * 128, cb, sbase, tid);
        CP_COMMIT();
    }

    // ---- epilogue: normalize, write Yh fp16 [B,T,C] ----
    const int b = bh >> 4, h = bh & 15;
#pragma unroll
    for (int mf = 0; mf < 2; mf++) {
        const float i0 = 1.f / lrun[mf][0];
        const float i1 = 1.f / lrun[mf][1];
        const int r0 = q0 + w * 32 + mf * 16 + gq;
        const int r1 = r0 + 8;
        const size_t base0 = ((size_t)b * TT + r0) * CC + h * DH;
        const size_t base1 = ((size_t)b * TT + r1) * CC + h * DH;
#pragma unroll
        for (int nf = 0; nf < 8; nf++) {
            const int col = nf * 8 + 2 * gt;
            *reinterpret_cast<__half2*>(&g_Yh[base0 + col]) =
                __floats2half2_rn(acc[mf][nf][0] * i0, acc[mf][nf][1] * i0);
            *reinterpret_cast<__half2*>(&g_Yh[base1 + col]) =
                __floats2half2_rn(acc[mf][nf][2] * i1, acc[mf][nf][3] * i1);
        }
    }
}

// ---------------------------------------------------------------------------
extern "C" void kernel_launch(void* const* d_in, const int* in_sizes, int n_in,
                              void* d_out, int out_size)
{
    const float* x  = (const float*)d_in[0];
    const float* Wq = (const float*)d_in[1];
    const float* bq = (const float*)d_in[2];
    const float* Wk = (const float*)d_in[3];
    const float* bk = (const float*)d_in[4];
    const float* Wv = (const float*)d_in[5];
    const float* bv = (const float*)d_in[6];
    const float* Wo = (const float*)d_in[7];
    const float* bo = (const float*)d_in[8];
    float* out = (float*)d_out;

    cudaFuncSetAttribute(gemm_qkv,
                         cudaFuncAttributeMaxDynamicSharedMemorySize, GEMM_SMEM_BYTES);
    cudaFuncSetAttribute(gemm_out,
                         cudaFuncAttributeMaxDynamicSharedMemorySize, GEMM_SMEM_BYTES);
    cudaFuncSetAttribute(flash_mma,
                         cudaFuncAttributeMaxDynamicSharedMemorySize, FL_BYTES);

    const size_t NCV = ((size_t)MM * CC + (size_t)4 * CC * CC) / 8;
    cvt_kernel<<<(unsigned)(NCV / 256), 256>>>(x, Wq, Wk, Wv, Wo);

    gemm_qkv<<<dim3(CC / 128, MM / 128, 3), 128, GEMM_SMEM_BYTES>>>(bq, bk, bv);

    flash_mma<<<dim3(TT / 128, BB * HH), 128, FL_BYTES>>>(out);

    gemm_out<<<dim3(CC / 128, MM / 128), 128, GEMM_SMEM_BYTES>>>(bo, out);
}